// round 10
// baseline (speedup 1.0000x reference)
#include <cuda_runtime.h>

#define NN 50000
#define NE 800000
#define DD 64
#define NL 5
#define SCAN_T 256
#define NTILES ((NN + SCAN_T - 1) / SCAN_T)
#define BN_EPS 1e-5f
#define GIN_BLOCKS 592
#define NPI 16   // nodes per block-iteration

// ---------------- device scratch (referenced ONLY from device code) -------
__device__ int d_deg[NN];
__device__ int d_rowptr[NN + 1];
__device__ int d_cursor[NN];
__device__ int d_srcidx[NE];
__device__ int d_part[NTILES];
__device__ int d_partx[NTILES];
__device__ int d_is64;
__device__ float d_stats[NL][2][DD];
__device__ __align__(16) float d_preA[NN * DD];
__device__ __align__(16) float d_preB[NN * DD];

__device__ __forceinline__ int edge_at(const void* e, long long idx) {
    if (d_is64) return (int)((const long long*)e)[idx];
    return ((const int*)e)[idx];
}

// ---------------- zero + dtype probe (fused) -------------------------------
__global__ void k_zero(const int* __restrict__ e) {
    int i = blockIdx.x * blockDim.x + threadIdx.x;
    if (i < NN) d_deg[i] = 0;
    if (i < NL * 2 * DD) ((float*)d_stats)[i] = 0.f;
    if (blockIdx.x == 0) {
        // int64 edges (values < 2^31) have all-zero odd 32-bit words
        __shared__ int any;
        if (threadIdx.x == 0) any = 0;
        __syncthreads();
        for (int j = threadIdx.x; j < 2048; j += blockDim.x)
            if (e[2 * j + 1] != 0) any = 1;
        __syncthreads();
        if (threadIdx.x == 0) d_is64 = any ? 0 : 1;
    }
}

// ---------------- CSR build ------------------------------------------------
__global__ void k_hist(const void* __restrict__ e) {
    int i = blockIdx.x * blockDim.x + threadIdx.x;
    if (i < NE) atomicAdd(&d_deg[edge_at(e, (long long)NE + i)], 1);
}

__global__ void k_scan1() {
    __shared__ int s[SCAN_T];
    int t = threadIdx.x, i = blockIdx.x * SCAN_T + t;
    s[t] = (i < NN) ? d_deg[i] : 0;
    __syncthreads();
    for (int off = SCAN_T / 2; off > 0; off >>= 1) {
        if (t < off) s[t] += s[t + off];
        __syncthreads();
    }
    if (t == 0) d_part[blockIdx.x] = s[0];
}

__global__ void k_scan2() {
    __shared__ int s[SCAN_T];
    int t = threadIdx.x;
    int v = (t < NTILES) ? d_part[t] : 0;
    s[t] = v;
    __syncthreads();
    for (int off = 1; off < SCAN_T; off <<= 1) {
        int x = (t >= off) ? s[t - off] : 0;
        __syncthreads();
        s[t] += x;
        __syncthreads();
    }
    if (t < NTILES) d_partx[t] = s[t] - v;
}

__global__ void k_scan3() {
    __shared__ int s[SCAN_T];
    int t = threadIdx.x, i = blockIdx.x * SCAN_T + t;
    int v = (i < NN) ? d_deg[i] : 0;
    s[t] = v;
    __syncthreads();
    for (int off = 1; off < SCAN_T; off <<= 1) {
        int x = (t >= off) ? s[t - off] : 0;
        __syncthreads();
        s[t] += x;
        __syncthreads();
    }
    if (i < NN) {
        int r = d_partx[blockIdx.x] + s[t] - v;
        d_rowptr[i] = r;
        d_cursor[i] = r;
    }
    if (i == 0) d_rowptr[NN] = NE;
}

__global__ void k_fill(const void* __restrict__ e) {
    int i = blockIdx.x * blockDim.x + threadIdx.x;
    if (i < NE) {
        int dst = edge_at(e, (long long)NE + i);
        int src = edge_at(e, i);
        int p = atomicAdd(&d_cursor[dst], 1);
        d_srcidx[p] = src;
    }
}

// ---------------- layer 0: D_IN=2 -> 64 -> d_preA + stats[0] --------------
__global__ __launch_bounds__(256) void k_gin0(
    const float* __restrict__ x2,
    const float* __restrict__ W1, const float* __restrict__ b1,
    const float* __restrict__ W2, const float* __restrict__ b2)
{
    __shared__ __align__(16) float sW2T[DD][DD + 4];  // [f][k]
    __shared__ float sW1[2 * DD];
    __shared__ float sb1[DD], sb2[DD];
    __shared__ float sagg[NPI][2];
    __shared__ __align__(16) float shid[NPI][DD];

    int tid = threadIdx.x;
    for (int i = tid; i < DD * DD; i += 256) {
        int k = i >> 6, f = i & 63;
        sW2T[f][k] = W2[i];
    }
    if (tid < 2 * DD) sW1[tid] = W1[tid];
    if (tid < DD) { sb1[tid] = b1[tid]; sb2[tid] = b2[tid]; }
    __syncthreads();

    const float2* __restrict__ x2v = (const float2*)x2;
    const int lane = tid & 31, w = tid >> 5;
    const int jset = tid >> 6, f = tid & 63;
    const int j0 = jset * 4;
    float lsum = 0.f, lsq = 0.f;
    const int G = gridDim.x * NPI;
    const int iters = (NN + G - 1) / G;

    for (int it = 0; it < iters; ++it) {
        const int base = blockIdx.x * NPI + it * G;

        #pragma unroll
        for (int r = 0; r < 2; ++r) {
            int ln = r * 8 + w;
            int n = base + ln;
            float a0 = 0.f, a1 = 0.f;
            if (n < NN) {
                if (lane == 0) {
                    float2 self = x2v[n];
                    a0 = self.x; a1 = self.y;
                }
                int r0 = d_rowptr[n], r1 = d_rowptr[n + 1];
                for (int e = r0 + lane; e < r1; e += 32) {
                    float2 v = x2v[d_srcidx[e]];
                    a0 += v.x; a1 += v.y;
                }
            }
            #pragma unroll
            for (int off = 16; off > 0; off >>= 1) {
                a0 += __shfl_down_sync(0xffffffffu, a0, off);
                a1 += __shfl_down_sync(0xffffffffu, a1, off);
            }
            if (lane == 0) { sagg[ln][0] = a0; sagg[ln][1] = a1; }
        }
        __syncthreads();

        {
            float w0 = sW1[f], w1 = sW1[DD + f], bb = sb1[f];
            #pragma unroll
            for (int j = 0; j < 4; ++j) {
                float t = fmaf(sagg[j0 + j][0], w0, fmaf(sagg[j0 + j][1], w1, bb));
                shid[j0 + j][f] = fmaxf(t, 0.f);
            }
        }
        __syncthreads();

        float p0 = sb2[f], p1 = p0, p2 = p0, p3 = p0;
        #pragma unroll
        for (int kq = 0; kq < DD / 4; ++kq) {
            float4 w4 = *(const float4*)&sW2T[f][kq * 4];
            float4 x0 = ((const float4*)shid[j0 + 0])[kq];
            float4 x1 = ((const float4*)shid[j0 + 1])[kq];
            float4 x2r = ((const float4*)shid[j0 + 2])[kq];
            float4 x3 = ((const float4*)shid[j0 + 3])[kq];
            p0 = fmaf(w4.x, x0.x, p0); p0 = fmaf(w4.y, x0.y, p0);
            p0 = fmaf(w4.z, x0.z, p0); p0 = fmaf(w4.w, x0.w, p0);
            p1 = fmaf(w4.x, x1.x, p1); p1 = fmaf(w4.y, x1.y, p1);
            p1 = fmaf(w4.z, x1.z, p1); p1 = fmaf(w4.w, x1.w, p1);
            p2 = fmaf(w4.x, x2r.x, p2); p2 = fmaf(w4.y, x2r.y, p2);
            p2 = fmaf(w4.z, x2r.z, p2); p2 = fmaf(w4.w, x2r.w, p2);
            p3 = fmaf(w4.x, x3.x, p3); p3 = fmaf(w4.y, x3.y, p3);
            p3 = fmaf(w4.z, x3.z, p3); p3 = fmaf(w4.w, x3.w, p3);
        }
        int n0 = base + j0;
        if (n0 + 0 < NN) { d_preA[(n0 + 0) * DD + f] = p0; lsum += p0; lsq += p0 * p0; }
        if (n0 + 1 < NN) { d_preA[(n0 + 1) * DD + f] = p1; lsum += p1; lsq += p1 * p1; }
        if (n0 + 2 < NN) { d_preA[(n0 + 2) * DD + f] = p2; lsum += p2; lsq += p2 * p2; }
        if (n0 + 3 < NN) { d_preA[(n0 + 3) * DD + f] = p3; lsum += p3; lsq += p3 * p3; }
        __syncthreads();
    }

    shid[jset][f] = lsum;
    shid[4 + jset][f] = lsq;
    __syncthreads();
    if (tid < DD) {
        float s0 = shid[0][tid] + shid[1][tid] + shid[2][tid] + shid[3][tid];
        float s1 = shid[4][tid] + shid[5][tid] + shid[6][tid] + shid[7][tid];
        atomicAdd(&d_stats[0][0][tid], s0);
        atomicAdd(&d_stats[0][1][tid], s1);
    }
}

// ---------------- layers 1..4: fused BN(prev)+ReLU + gather + MLP + stats --
__global__ __launch_bounds__(256) void k_gin(int xsel, int layer,
    const float* __restrict__ W1, const float* __restrict__ b1,
    const float* __restrict__ W2, const float* __restrict__ b2,
    const float* __restrict__ pg, const float* __restrict__ pb)
{
    __shared__ __align__(16) float sW1T[DD][DD + 4];  // [f][k]
    __shared__ __align__(16) float sW2T[DD][DD + 4];
    __shared__ float sb1[DD], sb2[DD];
    __shared__ float4 sa4[DD / 4], sbb4[DD / 4];      // prev-layer BN affine
    __shared__ float4 s4in[NPI][DD / 4];              // gathered inputs
    __shared__ __align__(16) float shid[NPI][DD];     // hidden after relu

    const float* __restrict__ xpre = xsel ? d_preA : d_preB;
    float* __restrict__ opre = xsel ? d_preB : d_preA;

    int tid = threadIdx.x;
    for (int i = tid; i < DD * DD; i += 256) {
        int k = i >> 6, f = i & 63;
        sW1T[f][k] = W1[i];
        sW2T[f][k] = W2[i];
    }
    if (tid < DD) {
        sb1[tid] = b1[tid];
        sb2[tid] = b2[tid];
        const float inv = 1.0f / (float)NN;
        float mu = d_stats[layer - 1][0][tid] * inv;
        float var = d_stats[layer - 1][1][tid] * inv - mu * mu;
        float rs = rsqrtf(var + BN_EPS);
        float a = rs * pg[tid];
        ((float*)sa4)[tid] = a;
        ((float*)sbb4)[tid] = pb[tid] - mu * a;
    }
    __syncthreads();

    const float4* __restrict__ x4 = (const float4*)xpre;
    const int lane = tid & 31, w = tid >> 5;
    const int q = lane & 15, slot = lane >> 4;
    const float4 a4 = sa4[q], b4 = sbb4[q];
    const int jset = tid >> 6, f = tid & 63;
    const int j0 = jset * 4;
    float lsum = 0.f, lsq = 0.f;
    const int G = gridDim.x * NPI;
    const int iters = (NN + G - 1) / G;

    for (int it = 0; it < iters; ++it) {
        const int base = blockIdx.x * NPI + it * G;

        // ---- gather: warp-per-node, fused BN+ReLU, 4x unrolled edges -----
        #pragma unroll
        for (int r = 0; r < 2; ++r) {
            int ln = r * 8 + w;
            int n = base + ln;
            float4 accA = make_float4(0.f, 0.f, 0.f, 0.f);
            float4 accB = make_float4(0.f, 0.f, 0.f, 0.f);
            if (n < NN) {
                if (slot == 0) {
                    float4 v = x4[n * (DD / 4) + q];
                    accA.x = fmaxf(fmaf(v.x, a4.x, b4.x), 0.f);
                    accA.y = fmaxf(fmaf(v.y, a4.y, b4.y), 0.f);
                    accA.z = fmaxf(fmaf(v.z, a4.z, b4.z), 0.f);
                    accA.w = fmaxf(fmaf(v.w, a4.w, b4.w), 0.f);
                }
                int r0 = d_rowptr[n], r1 = d_rowptr[n + 1];
                int e = r0 + slot;
                // 4 edges per slot per step (8 edges per warp-step):
                // batch the index loads, then 4 independent row loads.
                for (; e + 6 < r1; e += 8) {
                    int s0 = d_srcidx[e];
                    int s1 = d_srcidx[e + 2];
                    int s2 = d_srcidx[e + 4];
                    int s3 = d_srcidx[e + 6];
                    float4 v0 = x4[s0 * (DD / 4) + q];
                    float4 v1 = x4[s1 * (DD / 4) + q];
                    float4 v2 = x4[s2 * (DD / 4) + q];
                    float4 v3 = x4[s3 * (DD / 4) + q];
                    accA.x += fmaxf(fmaf(v0.x, a4.x, b4.x), 0.f);
                    accA.y += fmaxf(fmaf(v0.y, a4.y, b4.y), 0.f);
                    accA.z += fmaxf(fmaf(v0.z, a4.z, b4.z), 0.f);
                    accA.w += fmaxf(fmaf(v0.w, a4.w, b4.w), 0.f);
                    accB.x += fmaxf(fmaf(v1.x, a4.x, b4.x), 0.f);
                    accB.y += fmaxf(fmaf(v1.y, a4.y, b4.y), 0.f);
                    accB.z += fmaxf(fmaf(v1.z, a4.z, b4.z), 0.f);
                    accB.w += fmaxf(fmaf(v1.w, a4.w, b4.w), 0.f);
                    accA.x += fmaxf(fmaf(v2.x, a4.x, b4.x), 0.f);
                    accA.y += fmaxf(fmaf(v2.y, a4.y, b4.y), 0.f);
                    accA.z += fmaxf(fmaf(v2.z, a4.z, b4.z), 0.f);
                    accA.w += fmaxf(fmaf(v2.w, a4.w, b4.w), 0.f);
                    accB.x += fmaxf(fmaf(v3.x, a4.x, b4.x), 0.f);
                    accB.y += fmaxf(fmaf(v3.y, a4.y, b4.y), 0.f);
                    accB.z += fmaxf(fmaf(v3.z, a4.z, b4.z), 0.f);
                    accB.w += fmaxf(fmaf(v3.w, a4.w, b4.w), 0.f);
                }
                for (; e < r1; e += 2) {
                    float4 v = x4[d_srcidx[e] * (DD / 4) + q];
                    accA.x += fmaxf(fmaf(v.x, a4.x, b4.x), 0.f);
                    accA.y += fmaxf(fmaf(v.y, a4.y, b4.y), 0.f);
                    accA.z += fmaxf(fmaf(v.z, a4.z, b4.z), 0.f);
                    accA.w += fmaxf(fmaf(v.w, a4.w, b4.w), 0.f);
                }
            }
            float4 acc;
            acc.x = accA.x + accB.x;
            acc.y = accA.y + accB.y;
            acc.z = accA.z + accB.z;
            acc.w = accA.w + accB.w;
            acc.x += __shfl_xor_sync(0xffffffffu, acc.x, 16);
            acc.y += __shfl_xor_sync(0xffffffffu, acc.y, 16);
            acc.z += __shfl_xor_sync(0xffffffffu, acc.z, 16);
            acc.w += __shfl_xor_sync(0xffffffffu, acc.w, 16);
            if (slot == 0) s4in[ln][q] = acc;
        }
        __syncthreads();

        // ---- MLP1: 4 nodes per thread, float4 weights --------------------
        float h0 = sb1[f], h1 = h0, h2 = h0, h3 = h0;
        #pragma unroll
        for (int kq = 0; kq < DD / 4; ++kq) {
            float4 w4 = *(const float4*)&sW1T[f][kq * 4];
            float4 x0 = s4in[j0 + 0][kq];
            float4 x1 = s4in[j0 + 1][kq];
            float4 x2 = s4in[j0 + 2][kq];
            float4 x3 = s4in[j0 + 3][kq];
            h0 = fmaf(w4.x, x0.x, h0); h0 = fmaf(w4.y, x0.y, h0);
            h0 = fmaf(w4.z, x0.z, h0); h0 = fmaf(w4.w, x0.w, h0);
            h1 = fmaf(w4.x, x1.x, h1); h1 = fmaf(w4.y, x1.y, h1);
            h1 = fmaf(w4.z, x1.z, h1); h1 = fmaf(w4.w, x1.w, h1);
            h2 = fmaf(w4.x, x2.x, h2); h2 = fmaf(w4.y, x2.y, h2);
            h2 = fmaf(w4.z, x2.z, h2); h2 = fmaf(w4.w, x2.w, h2);
            h3 = fmaf(w4.x, x3.x, h3); h3 = fmaf(w4.y, x3.y, h3);
            h3 = fmaf(w4.z, x3.z, h3); h3 = fmaf(w4.w, x3.w, h3);
        }
        shid[j0 + 0][f] = fmaxf(h0, 0.f);
        shid[j0 + 1][f] = fmaxf(h1, 0.f);
        shid[j0 + 2][f] = fmaxf(h2, 0.f);
        shid[j0 + 3][f] = fmaxf(h3, 0.f);
        __syncthreads();

        // ---- MLP2: 4 nodes per thread ------------------------------------
        float p0 = sb2[f], p1 = p0, p2 = p0, p3 = p0;
        #pragma unroll
        for (int kq = 0; kq < DD / 4; ++kq) {
            float4 w4 = *(const float4*)&sW2T[f][kq * 4];
            float4 x0 = ((const float4*)shid[j0 + 0])[kq];
            float4 x1 = ((const float4*)shid[j0 + 1])[kq];
            float4 x2 = ((const float4*)shid[j0 + 2])[kq];
            float4 x3 = ((const float4*)shid[j0 + 3])[kq];
            p0 = fmaf(w4.x, x0.x, p0); p0 = fmaf(w4.y, x0.y, p0);
            p0 = fmaf(w4.z, x0.z, p0); p0 = fmaf(w4.w, x0.w, p0);
            p1 = fmaf(w4.x, x1.x, p1); p1 = fmaf(w4.y, x1.y, p1);
            p1 = fmaf(w4.z, x1.z, p1); p1 = fmaf(w4.w, x1.w, p1);
            p2 = fmaf(w4.x, x2.x, p2); p2 = fmaf(w4.y, x2.y, p2);
            p2 = fmaf(w4.z, x2.z, p2); p2 = fmaf(w4.w, x2.w, p2);
            p3 = fmaf(w4.x, x3.x, p3); p3 = fmaf(w4.y, x3.y, p3);
            p3 = fmaf(w4.z, x3.z, p3); p3 = fmaf(w4.w, x3.w, p3);
        }
        int n0 = base + j0;
        if (n0 + 0 < NN) { opre[(n0 + 0) * DD + f] = p0; lsum += p0; lsq += p0 * p0; }
        if (n0 + 1 < NN) { opre[(n0 + 1) * DD + f] = p1; lsum += p1; lsq += p1 * p1; }
        if (n0 + 2 < NN) { opre[(n0 + 2) * DD + f] = p2; lsum += p2; lsq += p2 * p2; }
        if (n0 + 3 < NN) { opre[(n0 + 3) * DD + f] = p3; lsum += p3; lsq += p3 * p3; }
        __syncthreads();
    }

    // ---- column-stat block reduction + atomics ---------------------------
    shid[jset][f] = lsum;
    shid[4 + jset][f] = lsq;
    __syncthreads();
    if (tid < DD) {
        float s0 = shid[0][tid] + shid[1][tid] + shid[2][tid] + shid[3][tid];
        float s1 = shid[4][tid] + shid[5][tid] + shid[6][tid] + shid[7][tid];
        atomicAdd(&d_stats[layer][0][tid], s0);
        atomicAdd(&d_stats[layer][1][tid], s1);
    }
}

// ---------------- final batchnorm (layer NL-1 stats, no relu) -> d_out -----
__global__ void k_bn(float* __restrict__ out,
                     const float* __restrict__ gamma, const float* __restrict__ beta)
{
    int i = blockIdx.x * blockDim.x + threadIdx.x;
    if (i >= NN * DD / 4) return;
    float4 h = ((const float4*)d_preA)[i];
    int fb = (i & (DD / 4 - 1)) << 2;
    const float inv = 1.0f / (float)NN;
    float hv[4] = {h.x, h.y, h.z, h.w};
    float o[4];
    #pragma unroll
    for (int j = 0; j < 4; ++j) {
        int fidx = fb + j;
        float mu = d_stats[NL - 1][0][fidx] * inv;
        float var = d_stats[NL - 1][1][fidx] * inv - mu * mu;
        float rs = rsqrtf(var + BN_EPS);
        o[j] = (hv[j] - mu) * rs * gamma[fidx] + beta[fidx];
    }
    ((float4*)out)[i] = make_float4(o[0], o[1], o[2], o[3]);
}

// ---------------- launch ---------------------------------------------------
extern "C" void kernel_launch(void* const* d_in, const int* in_sizes, int n_in,
                              void* d_out, int out_size)
{
    const float* nodes = (const float*)d_in[0];
    const void* edges = d_in[1];
    const float* W1_0 = (const float*)d_in[3];
    const float* b1_0 = (const float*)d_in[4];
    const float* W2_0 = (const float*)d_in[5];
    const float* b2_0 = (const float*)d_in[6];
    const float* W1 = (const float*)d_in[7];
    const float* b1 = (const float*)d_in[8];
    const float* W2 = (const float*)d_in[9];
    const float* b2 = (const float*)d_in[10];
    const float* gamma = (const float*)d_in[11];
    const float* beta = (const float*)d_in[12];
    float* out = (float*)d_out;

    k_zero<<<(NN + 255) / 256, 256>>>((const int*)edges);
    k_hist<<<(NE + 255) / 256, 256>>>(edges);
    k_scan1<<<NTILES, SCAN_T>>>();
    k_scan2<<<1, SCAN_T>>>();
    k_scan3<<<NTILES, SCAN_T>>>();
    k_fill<<<(NE + 255) / 256, 256>>>(edges);

    // layer 0: nodes -> d_preA (pre-BN), stats[0]
    k_gin0<<<GIN_BLOCKS, 256>>>(nodes, W1_0, b1_0, W2_0, b2_0);

    // layers 1..4: l odd reads preA writes preB (xsel=1); l even reverse.
    for (int l = 1; l < NL; ++l) {
        k_gin<<<GIN_BLOCKS, 256>>>(l & 1, l,
                                   W1 + (l - 1) * DD * DD, b1 + (l - 1) * DD,
                                   W2 + (l - 1) * DD * DD, b2 + (l - 1) * DD,
                                   gamma + (l - 1) * DD, beta + (l - 1) * DD);
    }

    // final BN (layer 4 wrote d_preA), no relu -> out
    const int bn_blocks = (NN * DD / 4 + 255) / 256;
    k_bn<<<bn_blocks, 256>>>(out, gamma + (NL - 1) * DD, beta + (NL - 1) * DD);
}

// round 14
// speedup vs baseline: 1.0444x; 1.0444x over previous
#include <cuda_runtime.h>

#define NN 50000
#define NE 800000
#define DD 64
#define NL 5
#define SCAN_T 256
#define NTILES ((NN + SCAN_T - 1) / SCAN_T)
#define BN_EPS 1e-5f
#define GIN_BLOCKS 592
#define NPI 16   // nodes per block-iteration

// ---------------- device scratch (referenced ONLY from device code) -------
__device__ int d_deg[NN];
__device__ int d_rowptr[NN + 1];
__device__ int d_cursor[NN];
__device__ int d_srcidx[NE];
__device__ int d_part[NTILES];
__device__ int d_is64;
__device__ float d_stats[NL][2][DD];
__device__ __align__(16) float d_preA[NN * DD];
__device__ __align__(16) float d_preB[NN * DD];

__device__ __forceinline__ int edge_at(const void* e, long long idx) {
    if (d_is64) return (int)((const long long*)e)[idx];
    return ((const int*)e)[idx];
}

// ---------------- zero + dtype probe (fused) -------------------------------
__global__ void k_zero(const int* __restrict__ e) {
    int i = blockIdx.x * blockDim.x + threadIdx.x;
    if (i < NN) d_deg[i] = 0;
    if (i < NL * 2 * DD) ((float*)d_stats)[i] = 0.f;
    if (blockIdx.x == 0) {
        // int64 edges (values < 2^31) have all-zero odd 32-bit words
        __shared__ int any;
        if (threadIdx.x == 0) any = 0;
        __syncthreads();
        for (int j = threadIdx.x; j < 2048; j += blockDim.x)
            if (e[2 * j + 1] != 0) any = 1;
        __syncthreads();
        if (threadIdx.x == 0) d_is64 = any ? 0 : 1;
    }
}

// ---------------- CSR build ------------------------------------------------
__global__ void k_hist(const void* __restrict__ e) {
    int i = blockIdx.x * blockDim.x + threadIdx.x;
    if (i < NE) atomicAdd(&d_deg[edge_at(e, (long long)NE + i)], 1);
}

__global__ void k_scan1() {
    __shared__ int s[SCAN_T];
    int t = threadIdx.x, i = blockIdx.x * SCAN_T + t;
    s[t] = (i < NN) ? d_deg[i] : 0;
    __syncthreads();
    for (int off = SCAN_T / 2; off > 0; off >>= 1) {
        if (t < off) s[t] += s[t + off];
        __syncthreads();
    }
    if (t == 0) d_part[blockIdx.x] = s[0];
}

// scan3 with scan2 folded in: each block tree-sums d_part[0..blockIdx-1]
// (<=196 values) for its tile prefix, then scans its tile of degrees.
__global__ void k_scan3() {
    __shared__ int s[SCAN_T];
    __shared__ int prefix;
    int t = threadIdx.x, i = blockIdx.x * SCAN_T + t;

    // tile prefix = sum of d_part for preceding tiles
    int pv = (t < blockIdx.x) ? d_part[t] : 0;
    s[t] = pv;
    __syncthreads();
    for (int off = SCAN_T / 2; off > 0; off >>= 1) {
        if (t < off) s[t] += s[t + off];
        __syncthreads();
    }
    if (t == 0) prefix = s[0];
    __syncthreads();

    // inclusive scan of this tile's degrees
    int v = (i < NN) ? d_deg[i] : 0;
    s[t] = v;
    __syncthreads();
    for (int off = 1; off < SCAN_T; off <<= 1) {
        int x = (t >= off) ? s[t - off] : 0;
        __syncthreads();
        s[t] += x;
        __syncthreads();
    }
    if (i < NN) {
        int r = prefix + s[t] - v;  // exclusive
        d_rowptr[i] = r;
        d_cursor[i] = r;
    }
    if (i == 0) d_rowptr[NN] = NE;
}

__global__ void k_fill(const void* __restrict__ e) {
    int i = blockIdx.x * blockDim.x + threadIdx.x;
    if (i < NE) {
        int dst = edge_at(e, (long long)NE + i);
        int src = edge_at(e, i);
        int p = atomicAdd(&d_cursor[dst], 1);
        d_srcidx[p] = src;
    }
}

// ---------------- layer 0: D_IN=2 -> 64 -> d_preA + stats[0] --------------
__global__ __launch_bounds__(256) void k_gin0(
    const float* __restrict__ x2,
    const float* __restrict__ W1, const float* __restrict__ b1,
    const float* __restrict__ W2, const float* __restrict__ b2)
{
    __shared__ __align__(16) float sW2T[DD][DD + 4];  // [f][k]
    __shared__ float sW1[2 * DD];
    __shared__ float sb1[DD], sb2[DD];
    __shared__ float sagg[NPI][2];
    __shared__ __align__(16) float shid[NPI][DD];

    int tid = threadIdx.x;
    for (int i = tid; i < DD * DD; i += 256) {
        int k = i >> 6, f = i & 63;
        sW2T[f][k] = W2[i];
    }
    if (tid < 2 * DD) sW1[tid] = W1[tid];
    if (tid < DD) { sb1[tid] = b1[tid]; sb2[tid] = b2[tid]; }
    __syncthreads();

    const float2* __restrict__ x2v = (const float2*)x2;
    const int lane = tid & 31, w = tid >> 5;
    const int jset = tid >> 6, f = tid & 63;
    const int j0 = jset * 4;
    float lsum = 0.f, lsq = 0.f;
    const int G = gridDim.x * NPI;
    const int iters = (NN + G - 1) / G;

    for (int it = 0; it < iters; ++it) {
        const int base = blockIdx.x * NPI + it * G;

        #pragma unroll
        for (int r = 0; r < 2; ++r) {
            int ln = r * 8 + w;
            int n = base + ln;
            float a0 = 0.f, a1 = 0.f;
            if (n < NN) {
                if (lane == 0) {
                    float2 self = x2v[n];
                    a0 = self.x; a1 = self.y;
                }
                int r0 = d_rowptr[n], r1 = d_rowptr[n + 1];
                for (int e = r0 + lane; e < r1; e += 32) {
                    float2 v = x2v[d_srcidx[e]];
                    a0 += v.x; a1 += v.y;
                }
            }
            #pragma unroll
            for (int off = 16; off > 0; off >>= 1) {
                a0 += __shfl_down_sync(0xffffffffu, a0, off);
                a1 += __shfl_down_sync(0xffffffffu, a1, off);
            }
            if (lane == 0) { sagg[ln][0] = a0; sagg[ln][1] = a1; }
        }
        __syncthreads();

        {
            float w0 = sW1[f], w1 = sW1[DD + f], bb = sb1[f];
            #pragma unroll
            for (int j = 0; j < 4; ++j) {
                float t = fmaf(sagg[j0 + j][0], w0, fmaf(sagg[j0 + j][1], w1, bb));
                shid[j0 + j][f] = fmaxf(t, 0.f);
            }
        }
        __syncthreads();

        float p0 = sb2[f], p1 = p0, p2 = p0, p3 = p0;
        #pragma unroll
        for (int kq = 0; kq < DD / 4; ++kq) {
            float4 w4 = *(const float4*)&sW2T[f][kq * 4];
            float4 x0 = ((const float4*)shid[j0 + 0])[kq];
            float4 x1 = ((const float4*)shid[j0 + 1])[kq];
            float4 x2r = ((const float4*)shid[j0 + 2])[kq];
            float4 x3 = ((const float4*)shid[j0 + 3])[kq];
            p0 = fmaf(w4.x, x0.x, p0); p0 = fmaf(w4.y, x0.y, p0);
            p0 = fmaf(w4.z, x0.z, p0); p0 = fmaf(w4.w, x0.w, p0);
            p1 = fmaf(w4.x, x1.x, p1); p1 = fmaf(w4.y, x1.y, p1);
            p1 = fmaf(w4.z, x1.z, p1); p1 = fmaf(w4.w, x1.w, p1);
            p2 = fmaf(w4.x, x2r.x, p2); p2 = fmaf(w4.y, x2r.y, p2);
            p2 = fmaf(w4.z, x2r.z, p2); p2 = fmaf(w4.w, x2r.w, p2);
            p3 = fmaf(w4.x, x3.x, p3); p3 = fmaf(w4.y, x3.y, p3);
            p3 = fmaf(w4.z, x3.z, p3); p3 = fmaf(w4.w, x3.w, p3);
        }
        int n0 = base + j0;
        if (n0 + 0 < NN) { d_preA[(n0 + 0) * DD + f] = p0; lsum += p0; lsq += p0 * p0; }
        if (n0 + 1 < NN) { d_preA[(n0 + 1) * DD + f] = p1; lsum += p1; lsq += p1 * p1; }
        if (n0 + 2 < NN) { d_preA[(n0 + 2) * DD + f] = p2; lsum += p2; lsq += p2 * p2; }
        if (n0 + 3 < NN) { d_preA[(n0 + 3) * DD + f] = p3; lsum += p3; lsq += p3 * p3; }
        // no end-of-iteration barrier: sagg rewrite is fenced by the
        // post-gather sync of the NEXT iteration; shid rewrite by its
        // post-MLP1 position relative to this iteration's MLP2 reads.
    }
    __syncthreads();  // protect shid reuse below against last MLP2 reads

    shid[jset][f] = lsum;
    shid[4 + jset][f] = lsq;
    __syncthreads();
    if (tid < DD) {
        float s0 = shid[0][tid] + shid[1][tid] + shid[2][tid] + shid[3][tid];
        float s1 = shid[4][tid] + shid[5][tid] + shid[6][tid] + shid[7][tid];
        atomicAdd(&d_stats[0][0][tid], s0);
        atomicAdd(&d_stats[0][1][tid], s1);
    }
}

// ---------------- layers 1..4: fused BN(prev)+ReLU + gather + MLP + stats --
// xsel=1: read preA write preB; xsel=0: reverse.
__global__ __launch_bounds__(256) void k_gin(int xsel, int layer,
    const float* __restrict__ W1, const float* __restrict__ b1,
    const float* __restrict__ W2, const float* __restrict__ b2,
    const float* __restrict__ pg, const float* __restrict__ pb)
{
    __shared__ __align__(16) float sW1T[DD][DD + 4];  // [f][k]
    __shared__ __align__(16) float sW2T[DD][DD + 4];
    __shared__ float sb1[DD], sb2[DD];
    __shared__ float4 sa4[DD / 4], sbb4[DD / 4];      // prev-layer BN affine
    __shared__ float4 s4in[NPI][DD / 4];              // gathered inputs
    __shared__ __align__(16) float shid[NPI][DD];     // hidden after relu

    const float* __restrict__ xpre = xsel ? d_preA : d_preB;
    float* __restrict__ opre = xsel ? d_preB : d_preA;

    int tid = threadIdx.x;
    for (int i = tid; i < DD * DD; i += 256) {
        int k = i >> 6, f = i & 63;
        sW1T[f][k] = W1[i];
        sW2T[f][k] = W2[i];
    }
    if (tid < DD) {
        sb1[tid] = b1[tid];
        sb2[tid] = b2[tid];
        const float inv = 1.0f / (float)NN;
        float mu = d_stats[layer - 1][0][tid] * inv;
        float var = d_stats[layer - 1][1][tid] * inv - mu * mu;
        float rs = rsqrtf(var + BN_EPS);
        float a = rs * pg[tid];
        ((float*)sa4)[tid] = a;
        ((float*)sbb4)[tid] = pb[tid] - mu * a;
    }
    __syncthreads();

    const float4* __restrict__ x4 = (const float4*)xpre;
    const int lane = tid & 31, w = tid >> 5;
    const int q = lane & 15, slot = lane >> 4;
    const float4 a4 = sa4[q], b4 = sbb4[q];
    const int jset = tid >> 6, f = tid & 63;
    const int j0 = jset * 4;
    float lsum = 0.f, lsq = 0.f;
    const int G = gridDim.x * NPI;
    const int iters = (NN + G - 1) / G;

    for (int it = 0; it < iters; ++it) {
        const int base = blockIdx.x * NPI + it * G;

        // ---- gather: 8 warps x 2 rounds, warp-per-node, fused BN+ReLU ----
        #pragma unroll
        for (int r = 0; r < 2; ++r) {
            int ln = r * 8 + w;
            int n = base + ln;
            float4 acc = make_float4(0.f, 0.f, 0.f, 0.f);
            if (n < NN) {
                if (slot == 0) {
                    float4 v = x4[n * (DD / 4) + q];
                    acc.x = fmaxf(fmaf(v.x, a4.x, b4.x), 0.f);
                    acc.y = fmaxf(fmaf(v.y, a4.y, b4.y), 0.f);
                    acc.z = fmaxf(fmaf(v.z, a4.z, b4.z), 0.f);
                    acc.w = fmaxf(fmaf(v.w, a4.w, b4.w), 0.f);
                }
                int r0 = d_rowptr[n], r1 = d_rowptr[n + 1];
                for (int e = r0 + slot; e < r1; e += 2) {
                    float4 v = x4[d_srcidx[e] * (DD / 4) + q];
                    acc.x += fmaxf(fmaf(v.x, a4.x, b4.x), 0.f);
                    acc.y += fmaxf(fmaf(v.y, a4.y, b4.y), 0.f);
                    acc.z += fmaxf(fmaf(v.z, a4.z, b4.z), 0.f);
                    acc.w += fmaxf(fmaf(v.w, a4.w, b4.w), 0.f);
                }
            }
            acc.x += __shfl_xor_sync(0xffffffffu, acc.x, 16);
            acc.y += __shfl_xor_sync(0xffffffffu, acc.y, 16);
            acc.z += __shfl_xor_sync(0xffffffffu, acc.z, 16);
            acc.w += __shfl_xor_sync(0xffffffffu, acc.w, 16);
            if (slot == 0) s4in[ln][q] = acc;
        }
        __syncthreads();

        // ---- MLP1: 4 nodes per thread, float4 weights --------------------
        float h0 = sb1[f], h1 = h0, h2 = h0, h3 = h0;
        #pragma unroll
        for (int kq = 0; kq < DD / 4; ++kq) {
            float4 w4 = *(const float4*)&sW1T[f][kq * 4];
            float4 x0 = s4in[j0 + 0][kq];
            float4 x1 = s4in[j0 + 1][kq];
            float4 x2 = s4in[j0 + 2][kq];
            float4 x3 = s4in[j0 + 3][kq];
            h0 = fmaf(w4.x, x0.x, h0); h0 = fmaf(w4.y, x0.y, h0);
            h0 = fmaf(w4.z, x0.z, h0); h0 = fmaf(w4.w, x0.w, h0);
            h1 = fmaf(w4.x, x1.x, h1); h1 = fmaf(w4.y, x1.y, h1);
            h1 = fmaf(w4.z, x1.z, h1); h1 = fmaf(w4.w, x1.w, h1);
            h2 = fmaf(w4.x, x2.x, h2); h2 = fmaf(w4.y, x2.y, h2);
            h2 = fmaf(w4.z, x2.z, h2); h2 = fmaf(w4.w, x2.w, h2);
            h3 = fmaf(w4.x, x3.x, h3); h3 = fmaf(w4.y, x3.y, h3);
            h3 = fmaf(w4.z, x3.z, h3); h3 = fmaf(w4.w, x3.w, h3);
        }
        shid[j0 + 0][f] = fmaxf(h0, 0.f);
        shid[j0 + 1][f] = fmaxf(h1, 0.f);
        shid[j0 + 2][f] = fmaxf(h2, 0.f);
        shid[j0 + 3][f] = fmaxf(h3, 0.f);
        __syncthreads();

        // ---- MLP2: 4 nodes per thread ------------------------------------
        float p0 = sb2[f], p1 = p0, p2 = p0, p3 = p0;
        #pragma unroll
        for (int kq = 0; kq < DD / 4; ++kq) {
            float4 w4 = *(const float4*)&sW2T[f][kq * 4];
            float4 x0 = ((const float4*)shid[j0 + 0])[kq];
            float4 x1 = ((const float4*)shid[j0 + 1])[kq];
            float4 x2 = ((const float4*)shid[j0 + 2])[kq];
            float4 x3 = ((const float4*)shid[j0 + 3])[kq];
            p0 = fmaf(w4.x, x0.x, p0); p0 = fmaf(w4.y, x0.y, p0);
            p0 = fmaf(w4.z, x0.z, p0); p0 = fmaf(w4.w, x0.w, p0);
            p1 = fmaf(w4.x, x1.x, p1); p1 = fmaf(w4.y, x1.y, p1);
            p1 = fmaf(w4.z, x1.z, p1); p1 = fmaf(w4.w, x1.w, p1);
            p2 = fmaf(w4.x, x2.x, p2); p2 = fmaf(w4.y, x2.y, p2);
            p2 = fmaf(w4.z, x2.z, p2); p2 = fmaf(w4.w, x2.w, p2);
            p3 = fmaf(w4.x, x3.x, p3); p3 = fmaf(w4.y, x3.y, p3);
            p3 = fmaf(w4.z, x3.z, p3); p3 = fmaf(w4.w, x3.w, p3);
        }
        int n0 = base + j0;
        if (n0 + 0 < NN) { opre[(n0 + 0) * DD + f] = p0; lsum += p0; lsq += p0 * p0; }
        if (n0 + 1 < NN) { opre[(n0 + 1) * DD + f] = p1; lsum += p1; lsq += p1 * p1; }
        if (n0 + 2 < NN) { opre[(n0 + 2) * DD + f] = p2; lsum += p2; lsq += p2 * p2; }
        if (n0 + 3 < NN) { opre[(n0 + 3) * DD + f] = p3; lsum += p3; lsq += p3 * p3; }
        // no end-of-iteration barrier (see dependence analysis):
        //  - s4in(it+1) writes are fenced from MLP1(it) reads by the
        //    post-MLP1 sync above;
        //  - shid(it+1) writes are fenced from MLP2(it) reads by the
        //    post-gather sync of iteration it+1.
    }
    __syncthreads();  // protect shid reuse below against last MLP2 reads

    // ---- column-stat block reduction + atomics ---------------------------
    shid[jset][f] = lsum;
    shid[4 + jset][f] = lsq;
    __syncthreads();
    if (tid < DD) {
        float s0 = shid[0][tid] + shid[1][tid] + shid[2][tid] + shid[3][tid];
        float s1 = shid[4][tid] + shid[5][tid] + shid[6][tid] + shid[7][tid];
        atomicAdd(&d_stats[layer][0][tid], s0);
        atomicAdd(&d_stats[layer][1][tid], s1);
    }
}

// ---------------- final batchnorm (layer NL-1 stats, no relu) -> d_out -----
__global__ void k_bn(float* __restrict__ out,
                     const float* __restrict__ gamma, const float* __restrict__ beta)
{
    int i = blockIdx.x * blockDim.x + threadIdx.x;
    if (i >= NN * DD / 4) return;
    float4 h = ((const float4*)d_preA)[i];
    int fb = (i & (DD / 4 - 1)) << 2;
    const float inv = 1.0f / (float)NN;
    float hv[4] = {h.x, h.y, h.z, h.w};
    float o[4];
    #pragma unroll
    for (int j = 0; j < 4; ++j) {
        int fidx = fb + j;
        float mu = d_stats[NL - 1][0][fidx] * inv;
        float var = d_stats[NL - 1][1][fidx] * inv - mu * mu;
        float rs = rsqrtf(var + BN_EPS);
        o[j] = (hv[j] - mu) * rs * gamma[fidx] + beta[fidx];
    }
    ((float4*)out)[i] = make_float4(o[0], o[1], o[2], o[3]);
}

// ---------------- launch ---------------------------------------------------
extern "C" void kernel_launch(void* const* d_in, const int* in_sizes, int n_in,
                              void* d_out, int out_size)
{
    const float* nodes = (const float*)d_in[0];
    const void* edges = d_in[1];
    const float* W1_0 = (const float*)d_in[3];
    const float* b1_0 = (const float*)d_in[4];
    const float* W2_0 = (const float*)d_in[5];
    const float* b2_0 = (const float*)d_in[6];
    const float* W1 = (const float*)d_in[7];
    const float* b1 = (const float*)d_in[8];
    const float* W2 = (const float*)d_in[9];
    const float* b2 = (const float*)d_in[10];
    const float* gamma = (const float*)d_in[11];
    const float* beta = (const float*)d_in[12];
    float* out = (float*)d_out;

    k_zero<<<(NN + 255) / 256, 256>>>((const int*)edges);
    k_hist<<<(NE + 255) / 256, 256>>>(edges);
    k_scan1<<<NTILES, SCAN_T>>>();
    k_scan3<<<NTILES, SCAN_T>>>();
    k_fill<<<(NE + 255) / 256, 256>>>(edges);

    // layer 0: nodes -> d_preA (pre-BN), stats[0]
    k_gin0<<<GIN_BLOCKS, 256>>>(nodes, W1_0, b1_0, W2_0, b2_0);

    // layers 1..4: l odd reads preA writes preB (xsel=1); l even reverse.
    for (int l = 1; l < NL; ++l) {
        k_gin<<<GIN_BLOCKS, 256>>>(l & 1, l,
                                   W1 + (l - 1) * DD * DD, b1 + (l - 1) * DD,
                                   W2 + (l - 1) * DD * DD, b2 + (l - 1) * DD,
                                   gamma + (l - 1) * DD, beta + (l - 1) * DD);
    }

    // final BN (layer 4 wrote d_preA), no relu -> out
    const int bn_blocks = (NN * DD / 4 + 255) / 256;
    k_bn<<<bn_blocks, 256>>>(out, gamma + (NL - 1) * DD, beta + (NL - 1) * DD);
}